// round 15
// baseline (speedup 1.0000x reference)
#include <cuda_runtime.h>
#include <cuda_fp16.h>
#include <cstdint>

// ---------------- problem constants ----------------
#define BB     256
#define LMAXV  512
#define NC     300   // NCOND (K of GEMM1)
#define NH     600   // NHID  (N of GEMM1)
#define KPAD   320   // K padded to 10*32 (only 300 real; 300..320 zeros)
#define NPAD   640   // N padded to 5*128

// ---------------- device scratch (no runtime allocs allowed) ----------------
// __device__ globals are zero-initialized at module load. g_ctx padding
// (k >= 300) and dead rows (l >= len) are NEVER written and stay zero forever.
__device__ float  g_pool[BB * NH];                      // pooled SUMS (pre-division)
__device__ float  g_gpart[8][BB * NC];                  // gate GEMM split-K partials
__device__ __half g_w1t[NPAD * KPAD];                   // W1^T fp16, [n][k]
__device__ __half g_ctx[(size_t)BB * LMAXV * KPAD];     // ctx fp16, [b][l][k]

// ---------------- helpers ----------------
__device__ __forceinline__ uint32_t s2u(const void* p) {
    uint32_t a;
    asm("{ .reg .u64 t; cvta.to.shared.u64 t, %1; cvt.u32.u64 %0, t; }" : "=r"(a) : "l"(p));
    return a;
}

__device__ __forceinline__ void cp16(uint32_t s, const void* g) {
    asm volatile("cp.async.cg.shared.global [%0], [%1], 16;" :: "r"(s), "l"(g));
}

// zero-fill variant: src_size=0 writes 16B of zeros without reading global
__device__ __forceinline__ void cp16z(uint32_t s, const void* g, uint32_t src_size) {
    asm volatile("cp.async.cg.shared.global [%0], [%1], 16, %2;"
                 :: "r"(s), "l"(g), "r"(src_size));
}

__device__ __forceinline__ void ldm_x4(uint32_t* r, uint32_t addr) {
    asm volatile("ldmatrix.sync.aligned.m8n8.x4.shared.b16 {%0,%1,%2,%3}, [%4];"
                 : "=r"(r[0]), "=r"(r[1]), "=r"(r[2]), "=r"(r[3]) : "r"(addr));
}

__device__ __forceinline__ void mma_f16(float* d, const uint32_t* a, const uint32_t* b) {
    asm volatile(
        "mma.sync.aligned.m16n8k16.row.col.f32.f16.f16.f32 "
        "{%0,%1,%2,%3}, {%4,%5,%6,%7}, {%8,%9}, {%0,%1,%2,%3};"
        : "+f"(d[0]), "+f"(d[1]), "+f"(d[2]), "+f"(d[3])
        : "r"(a[0]), "r"(a[1]), "r"(a[2]), "r"(a[3]), "r"(b[0]), "r"(b[1]));
}

// ---------------- fused prep+conv ----------------
// blocks [0, 1024): conv ctx fp32 -> fp16 KPAD layout — ONLY valid rows and
//                   ONLY the 75 real k4 slots (padding stays load-time zero)
// blocks [1024, 1424): W1 -> W1^T fp16 + zero g_pool
#define CONV_BLKS 1024
#define PREP_BLKS 400

__global__ __launch_bounds__(512)
void prep_conv_kernel(const float* __restrict__ ctx,
                      const int*   __restrict__ lengths,
                      const float* __restrict__ W1)
{
    const int bid = blockIdx.x;
    if (bid < CONV_BLKS) {
        const int mt = bid & 3, b = bid >> 2;
        int len = lengths[b]; if (len < 1) len = 1;
        if (mt * 128 >= len) return;
        int lrows = len - mt * 128;
        if (lrows > 128) lrows = 128;

        const size_t in_row0  = ((size_t)b * LMAXV + (size_t)mt * 128) * NC;
        const size_t out_row0 = ((size_t)b * LMAXV + (size_t)mt * 128) * KPAD;

        const int total = lrows * 75;
        for (int idx = threadIdx.x; idx < total; idx += 512) {
            int row = idx / 75, k4 = idx - row * 75;
            float4 v = *(const float4*)(ctx + in_row0 + (size_t)row * NC + k4 * 4);
            __half2 h01 = __floats2half2_rn(v.x, v.y);
            __half2 h23 = __floats2half2_rn(v.z, v.w);
            uint2 h = make_uint2(*(uint32_t*)&h01, *(uint32_t*)&h23);
            *(uint2*)((__half*)g_ctx + out_row0 + (size_t)row * KPAD + k4 * 4) = h;
        }
    } else {
        int idx = (bid - CONV_BLKS) * 512 + threadIdx.x;
        if (idx < NPAD * KPAD) {
            int n = idx / KPAD, k = idx % KPAD;
            float v = (n < NH && k < NC) ? W1[(size_t)k * NH + n] : 0.0f;
            g_w1t[idx] = __float2half_rn(v);
        }
        if (idx < BB * NH) g_pool[idx] = 0.0f;
    }
}

// ---------------- Kernel A: 3-stage cp.async fp16 mma GEMM1 + relu + masked pool ----
// grid = (nt=5, mt=4, b=256), 256 threads = 8 warps (4m x 2n), warp tile 32x64
// R13 structure (M=128, occ=2 — R14: M=256 at occ=1 regressed 14%).
// Guards: mOK (loop-invariant warp-uniform); fullN selects between TWO fully
// unrolled MMA bodies (np 0..4 vs np 0..2) — NOT per-np predicates (R12 trap).
// acc[] indices STATIC everywhere (Round 8: local-mem demotion).
#define TILE_B   (128 * 80)
#define STAGE_B  (2 * TILE_B)
#define SMEM_DYN (3 * STAGE_B)   // 61440

__global__ __launch_bounds__(256, 2)
void mma_pool_kernel(const int* __restrict__ lengths, const float* __restrict__ b1)
{
    extern __shared__ __align__(16) char dsm[];
    __shared__ float sbias[128];
    __shared__ float sred[128];

    const int nt = blockIdx.x, mt = blockIdx.y, b = blockIdx.z;
    int len = lengths[b]; if (len < 1) len = 1;
    if (mt * 128 >= len) return;

    const int tid  = threadIdx.x;
    const int warp = tid >> 5, lane = tid & 31;
    const int warp_m = (warp & 3) * 32;   // 4 warps along M
    const int warp_n = (warp >> 2) * 64;  // 2 warps along N

    const bool mOK = (mt * 128 + warp_m) < len;

    const int n0 = nt * 128;
    // fullN false ONLY for nt=4 / warp_n=64 (cols 576..640; valid ends at 600,
    // reduced body covers to col 608; cols 600..608 are zero-padded in B)
    const bool fullN = (n0 + warp_n + 64) <= NH;
    const uint32_t sb = s2u(dsm);

    const __half* gA = g_ctx + ((size_t)b * LMAXV + (size_t)mt * 128) * KPAD;
    const __half* gB = g_w1t + (size_t)n0 * KPAD;

    const int r0 = tid >> 2, q0 = tid & 3;   // rows 0..63
    const int r1 = 64 + r0;                  // rows 64..127
    const int lrows = len - mt * 128;        // valid rows in this tile
    const uint32_t szA0 = (r0 < lrows) ? 16u : 0u;
    const uint32_t szA1 = (r1 < lrows) ? 16u : 0u;

    if (tid < 128) {
        int j = n0 + tid;
        sbias[tid] = (j < NH) ? b1[j] : 0.0f;
        sred[tid] = 0.0f;
    }

    const int t = lane >> 3, r = lane & 7;
    const uint32_t aoff = (uint32_t)(((t & 1) * 8 + r) * 80 + (t >> 1) * 16);
    const uint32_t boff = (uint32_t)((((t >> 1) * 8) + r) * 80 + (t & 1) * 16);

    float acc[2][8][4];
    #pragma unroll
    for (int i = 0; i < 2; i++)
        #pragma unroll
        for (int j = 0; j < 8; j++)
            #pragma unroll
            for (int q = 0; q < 4; q++) acc[i][j][q] = 0.0f;

    auto stage = [&](int c, int s) {
        const uint32_t base = sb + s * STAGE_B;
        const int ke = c * 32 + q0 * 8;
        const uint32_t d0 = (uint32_t)(r0 * 80 + q0 * 16);
        const uint32_t d1 = (uint32_t)(r1 * 80 + q0 * 16);
        cp16z(base + d0,         gA + (size_t)r0 * KPAD + ke, szA0);
        cp16z(base + d1,         gA + (size_t)r1 * KPAD + ke, szA1);
        cp16(base + TILE_B + d0, gB + (size_t)r0 * KPAD + ke);
        cp16(base + TILE_B + d1, gB + (size_t)r1 * KPAD + ke);
        asm volatile("cp.async.commit_group;" ::: "memory");
    };

    stage(0, 0);
    stage(1, 1);

    for (int c = 0; c < 10; c++) {
        const int s = c - (c / 3) * 3;       // c % 3
        if (c + 1 < 10)
            asm volatile("cp.async.wait_group 1;" ::: "memory");
        else
            asm volatile("cp.async.wait_group 0;" ::: "memory");
        __syncthreads();

        if (c + 2 < 10) {
            int s2 = (c + 2) - ((c + 2) / 3) * 3;
            stage(c + 2, s2);
        }

        if (mOK) {
            const uint32_t uA = sb + s * STAGE_B;
            const uint32_t uB = uA + TILE_B;

            const int nks = (c == 9) ? 1 : 2;   // chunk 9: k>=304 zero padding
            if (fullN) {
                for (int ks = 0; ks < nks; ks++) {
                    uint32_t a[2][4];
                    #pragma unroll
                    for (int m2 = 0; m2 < 2; m2++)
                        ldm_x4(a[m2], uA + (uint32_t)((warp_m + m2 * 16) * 80 + ks * 32) + aoff);
                    #pragma unroll
                    for (int np = 0; np < 4; np++) {
                        uint32_t bf[4];
                        ldm_x4(bf, uB + (uint32_t)((warp_n + np * 16) * 80 + ks * 32) + boff);
                        #pragma unroll
                        for (int m2 = 0; m2 < 2; m2++) {
                            mma_f16(acc[m2][2 * np],     a[m2], bf);
                            mma_f16(acc[m2][2 * np + 1], a[m2], bf + 2);
                        }
                    }
                }
            } else {
                for (int ks = 0; ks < nks; ks++) {
                    uint32_t a[2][4];
                    #pragma unroll
                    for (int m2 = 0; m2 < 2; m2++)
                        ldm_x4(a[m2], uA + (uint32_t)((warp_m + m2 * 16) * 80 + ks * 32) + aoff);
                    #pragma unroll
                    for (int np = 0; np < 2; np++) {
                        uint32_t bf[4];
                        ldm_x4(bf, uB + (uint32_t)((warp_n + np * 16) * 80 + ks * 32) + boff);
                        #pragma unroll
                        for (int m2 = 0; m2 < 2; m2++) {
                            mma_f16(acc[m2][2 * np],     a[m2], bf);
                            mma_f16(acc[m2][2 * np + 1], a[m2], bf + 2);
                        }
                    }
                }
            }
        }
    }

    // ---- epilogue: bias + relu + row-mask + column sums ----
    __syncthreads();
    if (mOK) {
        const int lrow = lane >> 2;
        const int lcol = (lane & 3) * 2;
        const int gm_base = mt * 128 + warp_m;

        if (fullN) {
            #pragma unroll
            for (int n8 = 0; n8 < 8; n8++) {
                int ncc = warp_n + n8 * 8 + lcol;
                float be = sbias[ncc], bo = sbias[ncc + 1];
                float se = 0.0f, so = 0.0f;
                #pragma unroll
                for (int m2 = 0; m2 < 2; m2++) {
                    int row0 = gm_base + m2 * 16 + lrow;
                    bool v0 = row0 < len;
                    bool v1 = (row0 + 8) < len;
                    const float* a = acc[m2][n8];
                    if (v0) { se += fmaxf(a[0] + be, 0.0f); so += fmaxf(a[1] + bo, 0.0f); }
                    if (v1) { se += fmaxf(a[2] + be, 0.0f); so += fmaxf(a[3] + bo, 0.0f); }
                }
                #pragma unroll
                for (int d = 4; d < 32; d <<= 1) {
                    se += __shfl_xor_sync(0xffffffffu, se, d);
                    so += __shfl_xor_sync(0xffffffffu, so, d);
                }
                if (lane < 4) {
                    atomicAdd(&sred[ncc], se);
                    atomicAdd(&sred[ncc + 1], so);
                }
            }
        } else {
            #pragma unroll
            for (int n8 = 0; n8 < 4; n8++) {
                int ncc = warp_n + n8 * 8 + lcol;
                float be = sbias[ncc], bo = sbias[ncc + 1];
                float se = 0.0f, so = 0.0f;
                #pragma unroll
                for (int m2 = 0; m2 < 2; m2++) {
                    int row0 = gm_base + m2 * 16 + lrow;
                    bool v0 = row0 < len;
                    bool v1 = (row0 + 8) < len;
                    const float* a = acc[m2][n8];
                    if (v0) { se += fmaxf(a[0] + be, 0.0f); so += fmaxf(a[1] + bo, 0.0f); }
                    if (v1) { se += fmaxf(a[2] + be, 0.0f); so += fmaxf(a[3] + bo, 0.0f); }
                }
                #pragma unroll
                for (int d = 4; d < 32; d <<= 1) {
                    se += __shfl_xor_sync(0xffffffffu, se, d);
                    so += __shfl_xor_sync(0xffffffffu, so, d);
                }
                if (lane < 4) {
                    atomicAdd(&sred[ncc], se);
                    atomicAdd(&sred[ncc + 1], so);
                }
            }
        }
    }
    __syncthreads();
    if (tid < 128) {
        int j = n0 + tid;
        if (j < NH) atomicAdd(&g_pool[(size_t)b * NH + j], sred[tid]);
    }
}

// ---------------- gate phase 1: split-K partials (8-way, 8 batches/block) ----
// grid = (8 NH-eighths, 32 batch-groups), 320 threads
__global__ __launch_bounds__(320)
void gate1_kernel(const float* __restrict__ Wa, const int* __restrict__ lengths)
{
    __shared__ float ps[8][76];
    const int q  = blockIdx.x;           // NH eighth (75 rows)
    const int b0 = blockIdx.y * 8;       // batch group
    const int tid = threadIdx.x;

    for (int i = tid; i < 8 * 75; i += 320) {
        int g = i / 75, h = i - g * 75;
        int len = lengths[b0 + g]; if (len < 1) len = 1;
        ps[g][h] = g_pool[(size_t)(b0 + g) * NH + q * 75 + h] / (float)len;
    }
    __syncthreads();

    const int j = tid;
    if (j < NC) {
        float a0 = 0.f, a1 = 0.f, a2 = 0.f, a3 = 0.f;
        float a4 = 0.f, a5 = 0.f, a6 = 0.f, a7 = 0.f;
        const float* w = Wa + (size_t)q * 75 * NC + j;
        #pragma unroll 5
        for (int h = 0; h < 75; h++) {
            float wv = __ldg(w + (size_t)h * NC);
            a0 = fmaf(ps[0][h], wv, a0);
            a1 = fmaf(ps[1][h], wv, a1);
            a2 = fmaf(ps[2][h], wv, a2);
            a3 = fmaf(ps[3][h], wv, a3);
            a4 = fmaf(ps[4][h], wv, a4);
            a5 = fmaf(ps[5][h], wv, a5);
            a6 = fmaf(ps[6][h], wv, a6);
            a7 = fmaf(ps[7][h], wv, a7);
        }
        float* gp = g_gpart[q];
        gp[(size_t)(b0 + 0) * NC + j] = a0;
        gp[(size_t)(b0 + 1) * NC + j] = a1;
        gp[(size_t)(b0 + 2) * NC + j] = a2;
        gp[(size_t)(b0 + 3) * NC + j] = a3;
        gp[(size_t)(b0 + 4) * NC + j] = a4;
        gp[(size_t)(b0 + 5) * NC + j] = a5;
        gp[(size_t)(b0 + 6) * NC + j] = a6;
        gp[(size_t)(b0 + 7) * NC + j] = a7;
    }
}

// ---------------- gate phase 2: sigmoid finisher ----------------
__global__ __launch_bounds__(256)
void gate2_kernel(const float* __restrict__ x,
                  const float* __restrict__ ba,
                  float*       __restrict__ out)
{
    int idx = blockIdx.x * 256 + threadIdx.x;
    if (idx < BB * NC) {
        int j = idx % NC;
        float z = ba[j];
        #pragma unroll
        for (int q = 0; q < 8; q++) z += g_gpart[q][idx];
        float g = 1.0f / (1.0f + expf(-z));
        out[idx] = g * x[idx];
    }
}

// ---------------- launch ----------------
// metadata order: x, context, lengths, W1, b1, Wa, ba
extern "C" void kernel_launch(void* const* d_in, const int* in_sizes, int n_in,
                              void* d_out, int out_size)
{
    const float* x       = (const float*)d_in[0];
    const float* context = (const float*)d_in[1];
    const int*   lengths = (const int*)  d_in[2];
    const float* W1      = (const float*)d_in[3];
    const float* b1      = (const float*)d_in[4];
    const float* Wa      = (const float*)d_in[5];
    const float* ba      = (const float*)d_in[6];
    float* out = (float*)d_out;

    cudaFuncSetAttribute(mma_pool_kernel,
                         cudaFuncAttributeMaxDynamicSharedMemorySize, SMEM_DYN);

    prep_conv_kernel<<<CONV_BLKS + PREP_BLKS, 512>>>(context, lengths, W1);

    dim3 grid(5, 4, BB);
    mma_pool_kernel<<<grid, 256, SMEM_DYN>>>(lengths, b1);

    dim3 g1(8, BB / 8);
    gate1_kernel<<<g1, 320>>>(Wa, lengths);

    gate2_kernel<<<(BB * NC + 255) / 256, 256>>>(x, ba, out);
}

// round 16
// speedup vs baseline: 1.4567x; 1.4567x over previous
#include <cuda_runtime.h>
#include <cuda_fp16.h>
#include <cstdint>

// ---------------- problem constants ----------------
#define BB     256
#define LMAXV  512
#define NC     300   // NCOND (K of GEMM1)
#define NH     600   // NHID  (N of GEMM1)
#define KPAD   320   // K padded to 10*32 (only 300 real; 300..320 zeros)
#define NPAD   640   // N padded to 5*128

// ---------------- device scratch (no runtime allocs allowed) ----------------
// __device__ globals are zero-initialized at module load. g_ctx padding
// (k >= 300) and dead rows (l >= len) are NEVER written and stay zero forever.
__device__ float  g_pool[BB * NH];                      // pooled SUMS (pre-division)
__device__ float  g_gpart[8][BB * NC];                  // gate GEMM split-K partials
__device__ __half g_w1t[NPAD * KPAD];                   // W1^T fp16, [n][k]
__device__ __half g_ctx[(size_t)BB * LMAXV * KPAD];     // ctx fp16, [b][l][k]

// ---------------- helpers ----------------
__device__ __forceinline__ uint32_t s2u(const void* p) {
    uint32_t a;
    asm("{ .reg .u64 t; cvta.to.shared.u64 t, %1; cvt.u32.u64 %0, t; }" : "=r"(a) : "l"(p));
    return a;
}

__device__ __forceinline__ void cp16(uint32_t s, const void* g) {
    asm volatile("cp.async.cg.shared.global [%0], [%1], 16;" :: "r"(s), "l"(g));
}

// zero-fill variant: src_size=0 writes 16B of zeros without reading global
__device__ __forceinline__ void cp16z(uint32_t s, const void* g, uint32_t src_size) {
    asm volatile("cp.async.cg.shared.global [%0], [%1], 16, %2;"
                 :: "r"(s), "l"(g), "r"(src_size));
}

__device__ __forceinline__ void ldm_x4(uint32_t* r, uint32_t addr) {
    asm volatile("ldmatrix.sync.aligned.m8n8.x4.shared.b16 {%0,%1,%2,%3}, [%4];"
                 : "=r"(r[0]), "=r"(r[1]), "=r"(r[2]), "=r"(r[3]) : "r"(addr));
}

__device__ __forceinline__ void mma_f16(float* d, const uint32_t* a, const uint32_t* b) {
    asm volatile(
        "mma.sync.aligned.m16n8k16.row.col.f32.f16.f16.f32 "
        "{%0,%1,%2,%3}, {%4,%5,%6,%7}, {%8,%9}, {%0,%1,%2,%3};"
        : "+f"(d[0]), "+f"(d[1]), "+f"(d[2]), "+f"(d[3])
        : "r"(a[0]), "r"(a[1]), "r"(a[2]), "r"(a[3]), "r"(b[0]), "r"(b[1]));
}

// ---------------- fused prep+conv ----------------
// blocks [0, 1024): conv ctx fp32 -> fp16 KPAD layout — ONLY valid rows and
//                   ONLY the 75 real k4 slots (padding stays load-time zero)
// blocks [1024, 1424): W1 -> W1^T fp16 + zero g_pool
#define CONV_BLKS 1024
#define PREP_BLKS 400

__global__ __launch_bounds__(512)
void prep_conv_kernel(const float* __restrict__ ctx,
                      const int*   __restrict__ lengths,
                      const float* __restrict__ W1)
{
    const int bid = blockIdx.x;
    if (bid < CONV_BLKS) {
        const int mt = bid & 3, b = bid >> 2;
        int len = lengths[b]; if (len < 1) len = 1;
        if (mt * 128 >= len) return;
        int lrows = len - mt * 128;
        if (lrows > 128) lrows = 128;

        const size_t in_row0  = ((size_t)b * LMAXV + (size_t)mt * 128) * NC;
        const size_t out_row0 = ((size_t)b * LMAXV + (size_t)mt * 128) * KPAD;

        const int total = lrows * 75;
        for (int idx = threadIdx.x; idx < total; idx += 512) {
            int row = idx / 75, k4 = idx - row * 75;
            float4 v = *(const float4*)(ctx + in_row0 + (size_t)row * NC + k4 * 4);
            __half2 h01 = __floats2half2_rn(v.x, v.y);
            __half2 h23 = __floats2half2_rn(v.z, v.w);
            uint2 h = make_uint2(*(uint32_t*)&h01, *(uint32_t*)&h23);
            *(uint2*)((__half*)g_ctx + out_row0 + (size_t)row * KPAD + k4 * 4) = h;
        }
    } else {
        int idx = (bid - CONV_BLKS) * 512 + threadIdx.x;
        if (idx < NPAD * KPAD) {
            int n = idx / KPAD, k = idx % KPAD;
            float v = (n < NH && k < NC) ? W1[(size_t)k * NH + n] : 0.0f;
            g_w1t[idx] = __float2half_rn(v);
        }
        if (idx < BB * NH) g_pool[idx] = 0.0f;
    }
}

// ---------------- Kernel A: 3-stage cp.async fp16 mma GEMM1 + relu + masked pool ----
// grid = (nt=5, mt=4, b=256), 256 threads = 8 warps (4m x 2n), warp tile 32x64
// EXACT R13 structure + A dead-row zfill ONLY. Hard-won constraints:
//   - acc[] indices STATIC (R8: runtime indexing -> local mem, 3.6x regression)
//   - mOK is the ONLY guard; no per-np predicates (R12), no dual bodies (R15:
//     body duplication -> register spill, +74us)
//   - M=128 / occ=2 (R14: M=256 at occ=1 regressed 14%)
#define TILE_B   (128 * 80)
#define STAGE_B  (2 * TILE_B)
#define SMEM_DYN (3 * STAGE_B)   // 61440

__global__ __launch_bounds__(256, 2)
void mma_pool_kernel(const int* __restrict__ lengths, const float* __restrict__ b1)
{
    extern __shared__ __align__(16) char dsm[];
    __shared__ float sbias[128];
    __shared__ float sred[128];

    const int nt = blockIdx.x, mt = blockIdx.y, b = blockIdx.z;
    int len = lengths[b]; if (len < 1) len = 1;
    if (mt * 128 >= len) return;

    const int tid  = threadIdx.x;
    const int warp = tid >> 5, lane = tid & 31;
    const int warp_m = (warp & 3) * 32;   // 4 warps along M
    const int warp_n = (warp >> 2) * 64;  // 2 warps along N

    const bool mOK = (mt * 128 + warp_m) < len;

    const int n0 = nt * 128;
    const uint32_t sb = s2u(dsm);

    const __half* gA = g_ctx + ((size_t)b * LMAXV + (size_t)mt * 128) * KPAD;
    const __half* gB = g_w1t + (size_t)n0 * KPAD;

    const int r0 = tid >> 2, q0 = tid & 3;   // rows 0..63
    const int r1 = 64 + r0;                  // rows 64..127
    const int lrows = len - mt * 128;        // valid rows in this tile
    const uint32_t szA0 = (r0 < lrows) ? 16u : 0u;
    const uint32_t szA1 = (r1 < lrows) ? 16u : 0u;

    if (tid < 128) {
        int j = n0 + tid;
        sbias[tid] = (j < NH) ? b1[j] : 0.0f;
        sred[tid] = 0.0f;
    }

    const int t = lane >> 3, r = lane & 7;
    const uint32_t aoff = (uint32_t)(((t & 1) * 8 + r) * 80 + (t >> 1) * 16);
    const uint32_t boff = (uint32_t)((((t >> 1) * 8) + r) * 80 + (t & 1) * 16);

    float acc[2][8][4];
    #pragma unroll
    for (int i = 0; i < 2; i++)
        #pragma unroll
        for (int j = 0; j < 8; j++)
            #pragma unroll
            for (int q = 0; q < 4; q++) acc[i][j][q] = 0.0f;

    auto stage = [&](int c, int s) {
        const uint32_t base = sb + s * STAGE_B;
        const int ke = c * 32 + q0 * 8;
        const uint32_t d0 = (uint32_t)(r0 * 80 + q0 * 16);
        const uint32_t d1 = (uint32_t)(r1 * 80 + q0 * 16);
        cp16z(base + d0,         gA + (size_t)r0 * KPAD + ke, szA0);
        cp16z(base + d1,         gA + (size_t)r1 * KPAD + ke, szA1);
        cp16(base + TILE_B + d0, gB + (size_t)r0 * KPAD + ke);
        cp16(base + TILE_B + d1, gB + (size_t)r1 * KPAD + ke);
        asm volatile("cp.async.commit_group;" ::: "memory");
    };

    stage(0, 0);
    stage(1, 1);

    for (int c = 0; c < 10; c++) {
        const int s = c - (c / 3) * 3;       // c % 3
        if (c + 1 < 10)
            asm volatile("cp.async.wait_group 1;" ::: "memory");
        else
            asm volatile("cp.async.wait_group 0;" ::: "memory");
        __syncthreads();

        if (c + 2 < 10) {
            int s2 = (c + 2) - ((c + 2) / 3) * 3;
            stage(c + 2, s2);
        }

        if (mOK) {
            const uint32_t uA = sb + s * STAGE_B;
            const uint32_t uB = uA + TILE_B;

            const int nks = (c == 9) ? 1 : 2;   // chunk 9: k>=304 zero padding
            for (int ks = 0; ks < nks; ks++) {
                uint32_t a[2][4];
                #pragma unroll
                for (int m2 = 0; m2 < 2; m2++)
                    ldm_x4(a[m2], uA + (uint32_t)((warp_m + m2 * 16) * 80 + ks * 32) + aoff);
                #pragma unroll
                for (int np = 0; np < 4; np++) {
                    uint32_t bf[4];
                    ldm_x4(bf, uB + (uint32_t)((warp_n + np * 16) * 80 + ks * 32) + boff);
                    #pragma unroll
                    for (int m2 = 0; m2 < 2; m2++) {
                        mma_f16(acc[m2][2 * np],     a[m2], bf);
                        mma_f16(acc[m2][2 * np + 1], a[m2], bf + 2);
                    }
                }
            }
        }
    }

    // ---- epilogue: bias + relu + row-mask + column sums ----
    __syncthreads();
    if (mOK) {
        const int lrow = lane >> 2;
        const int lcol = (lane & 3) * 2;
        const int gm_base = mt * 128 + warp_m;

        #pragma unroll
        for (int n8 = 0; n8 < 8; n8++) {
            int ncc = warp_n + n8 * 8 + lcol;
            float be = sbias[ncc], bo = sbias[ncc + 1];
            float se = 0.0f, so = 0.0f;
            #pragma unroll
            for (int m2 = 0; m2 < 2; m2++) {
                int row0 = gm_base + m2 * 16 + lrow;
                bool v0 = row0 < len;
                bool v1 = (row0 + 8) < len;
                const float* a = acc[m2][n8];
                if (v0) { se += fmaxf(a[0] + be, 0.0f); so += fmaxf(a[1] + bo, 0.0f); }
                if (v1) { se += fmaxf(a[2] + be, 0.0f); so += fmaxf(a[3] + bo, 0.0f); }
            }
            #pragma unroll
            for (int d = 4; d < 32; d <<= 1) {
                se += __shfl_xor_sync(0xffffffffu, se, d);
                so += __shfl_xor_sync(0xffffffffu, so, d);
            }
            if (lane < 4) {
                atomicAdd(&sred[ncc], se);
                atomicAdd(&sred[ncc + 1], so);
            }
        }
    }
    __syncthreads();
    if (tid < 128) {
        int j = n0 + tid;
        if (j < NH) atomicAdd(&g_pool[(size_t)b * NH + j], sred[tid]);
    }
}

// ---------------- gate phase 1: split-K partials (8-way, 8 batches/block) ----
// grid = (8 NH-eighths, 32 batch-groups), 320 threads
__global__ __launch_bounds__(320)
void gate1_kernel(const float* __restrict__ Wa, const int* __restrict__ lengths)
{
    __shared__ float ps[8][76];
    const int q  = blockIdx.x;           // NH eighth (75 rows)
    const int b0 = blockIdx.y * 8;       // batch group
    const int tid = threadIdx.x;

    for (int i = tid; i < 8 * 75; i += 320) {
        int g = i / 75, h = i - g * 75;
        int len = lengths[b0 + g]; if (len < 1) len = 1;
        ps[g][h] = g_pool[(size_t)(b0 + g) * NH + q * 75 + h] / (float)len;
    }
    __syncthreads();

    const int j = tid;
    if (j < NC) {
        float a0 = 0.f, a1 = 0.f, a2 = 0.f, a3 = 0.f;
        float a4 = 0.f, a5 = 0.f, a6 = 0.f, a7 = 0.f;
        const float* w = Wa + (size_t)q * 75 * NC + j;
        #pragma unroll 5
        for (int h = 0; h < 75; h++) {
            float wv = __ldg(w + (size_t)h * NC);
            a0 = fmaf(ps[0][h], wv, a0);
            a1 = fmaf(ps[1][h], wv, a1);
            a2 = fmaf(ps[2][h], wv, a2);
            a3 = fmaf(ps[3][h], wv, a3);
            a4 = fmaf(ps[4][h], wv, a4);
            a5 = fmaf(ps[5][h], wv, a5);
            a6 = fmaf(ps[6][h], wv, a6);
            a7 = fmaf(ps[7][h], wv, a7);
        }
        float* gp = g_gpart[q];
        gp[(size_t)(b0 + 0) * NC + j] = a0;
        gp[(size_t)(b0 + 1) * NC + j] = a1;
        gp[(size_t)(b0 + 2) * NC + j] = a2;
        gp[(size_t)(b0 + 3) * NC + j] = a3;
        gp[(size_t)(b0 + 4) * NC + j] = a4;
        gp[(size_t)(b0 + 5) * NC + j] = a5;
        gp[(size_t)(b0 + 6) * NC + j] = a6;
        gp[(size_t)(b0 + 7) * NC + j] = a7;
    }
}

// ---------------- gate phase 2: sigmoid finisher ----------------
__global__ __launch_bounds__(256)
void gate2_kernel(const float* __restrict__ x,
                  const float* __restrict__ ba,
                  float*       __restrict__ out)
{
    int idx = blockIdx.x * 256 + threadIdx.x;
    if (idx < BB * NC) {
        int j = idx % NC;
        float z = ba[j];
        #pragma unroll
        for (int q = 0; q < 8; q++) z += g_gpart[q][idx];
        float g = 1.0f / (1.0f + expf(-z));
        out[idx] = g * x[idx];
    }
}

// ---------------- launch ----------------
// metadata order: x, context, lengths, W1, b1, Wa, ba
extern "C" void kernel_launch(void* const* d_in, const int* in_sizes, int n_in,
                              void* d_out, int out_size)
{
    const float* x       = (const float*)d_in[0];
    const float* context = (const float*)d_in[1];
    const int*   lengths = (const int*)  d_in[2];
    const float* W1      = (const float*)d_in[3];
    const float* b1      = (const float*)d_in[4];
    const float* Wa      = (const float*)d_in[5];
    const float* ba      = (const float*)d_in[6];
    float* out = (float*)d_out;

    cudaFuncSetAttribute(mma_pool_kernel,
                         cudaFuncAttributeMaxDynamicSharedMemorySize, SMEM_DYN);

    prep_conv_kernel<<<CONV_BLKS + PREP_BLKS, 512>>>(context, lengths, W1);

    dim3 grid(5, 4, BB);
    mma_pool_kernel<<<grid, 256, SMEM_DYN>>>(lengths, b1);

    dim3 g1(8, BB / 8);
    gate1_kernel<<<g1, 320>>>(Wa, lengths);

    gate2_kernel<<<(BB * NC + 255) / 256, 256>>>(x, ba, out);
}